// round 17
// baseline (speedup 1.0000x reference)
#include <cuda_runtime.h>
#include <cstdint>

// Problem constants
#define MTOT   32768      // B*S
#define DM     512        // d_model
#define HEADS  8
#define HD     64
#define WSZ    128
#define NWIN   256

// ---------------------------------------------------------------------------
// Scratch (device globals; no runtime allocation allowed)
// ---------------------------------------------------------------------------
__device__ float g_q [MTOT * DM];     // head-major [win][head][128][64]
__device__ float g_k [MTOT * DM];     // head-major
__device__ float g_v [MTOT * DM];     // head-major
__device__ float g_ao[MTOT * DM];     // flat [row][512]
__device__ float g_xr[MTOT * DM];     // x pre-rounded to tf32
__device__ float g_wr[4][DM * DM];    // Wq,Wk,Wv,Wp pre-rounded (contiguous)

// ---------------------------------------------------------------------------
// helpers
// ---------------------------------------------------------------------------
__device__ __forceinline__ uint32_t f2tf32(float f) {
    uint32_t r;
    asm("cvt.rna.tf32.f32 %0, %1;" : "=r"(r) : "f"(f));
    return r;
}
__device__ __forceinline__ float f2tf32f(float f) {
    return __uint_as_float(f2tf32(f));
}

// mma.sync m16n8k8 tf32 (baseline PTX; valid on plain sm_103 target)
__device__ __forceinline__ void mma8(float* d, const uint32_t* a, const uint32_t* b) {
    asm volatile(
        "mma.sync.aligned.m16n8k8.row.col.f32.tf32.tf32.f32 "
        "{%0,%1,%2,%3}, {%4,%5,%6,%7}, {%8,%9}, {%0,%1,%2,%3};"
        : "+f"(d[0]), "+f"(d[1]), "+f"(d[2]), "+f"(d[3])
        : "r"(a[0]), "r"(a[1]), "r"(a[2]), "r"(a[3]), "r"(b[0]), "r"(b[1]));
}

// Fast exp on FMA/ALU pipes only (no MUFU, no CVT). x <= 0 here.
__device__ __forceinline__ float fexp(float x) {
    float y = x * 1.44269504088896f;
    float t = y + 12582912.f;
    float n = t - 12582912.f;
    float f = y - n;
    float p = 0.00133335581f;
    p = fmaf(p, f, 0.00961812910f);
    p = fmaf(p, f, 0.05550410866f);
    p = fmaf(p, f, 0.24022650696f);
    p = fmaf(p, f, 0.69314718056f);
    p = fmaf(p, f, 1.0f);
    int ni = __float_as_int(t) - 0x4B400000;
    float s = __int_as_float((ni + 127) << 23);
    return p * s;
}

#define CP_ASYNC16(dst_u32, src_ptr) \
    asm volatile("cp.async.cg.shared.global [%0], [%1], 16;" \
                 :: "r"(dst_u32), "l"(src_ptr))
#define CP_COMMIT() asm volatile("cp.async.commit_group;" ::: "memory")
#define CP_WAIT1()  asm volatile("cp.async.wait_group 1;" ::: "memory")
#define CP_WAIT0()  asm volatile("cp.async.wait_group 0;" ::: "memory")

// ---------------------------------------------------------------------------
// Pre-pass kernels: round fp32 -> tf32 bits (stored as float)
// ---------------------------------------------------------------------------
__global__ __launch_bounds__(256) void cvt_tf32(const float* __restrict__ in,
                                                float* __restrict__ out, int n4)
{
    int i = blockIdx.x * 256 + threadIdx.x;
    if (i < n4) {
        float4 v = ((const float4*)in)[i];
        ((float4*)out)[i] = make_float4(f2tf32f(v.x), f2tf32f(v.y),
                                        f2tf32f(v.z), f2tf32f(v.w));
    }
}

__global__ __launch_bounds__(256) void cvt_w4(
    const float* __restrict__ w0, const float* __restrict__ w1,
    const float* __restrict__ w2, const float* __restrict__ w3,
    float* __restrict__ out)
{
    const int which = blockIdx.y;
    const float* in = (which == 0) ? w0 : (which == 1) ? w1 : (which == 2) ? w2 : w3;
    const int n4 = DM * DM / 4;
    int i = blockIdx.x * 256 + threadIdx.x;
    if (i < n4) {
        float4 v = ((const float4*)in)[i];
        ((float4*)(out + (size_t)which * DM * DM))[i] =
            make_float4(f2tf32f(v.x), f2tf32f(v.y), f2tf32f(v.z), f2tf32f(v.w));
    }
}

// ---------------------------------------------------------------------------
// tf32 tensor GEMM v7: CTA tile 256x128, 8 warps as 4m x 2n (warp 64x64).
// 3-stage cp.async pipeline, SW128 16B-chunk swizzle (j ^ (r&7)).
// 1 CTA/SM (144KB smem). Bigger warp tiles cut smem fragment traffic 3x
// per FLOP (crossbar-bound fix). Accumulation order identical to v6.
// ---------------------------------------------------------------------------
#define KC     32
#define NCH    (DM / KC)           // 16
#define NST    3
#define TILEWA (256 * 32)          // 8192 words = 32 KB
#define TILEWB (128 * 32)          // 4096 words = 16 KB
#define STAGEW (TILEWA + TILEWB)   // 12288 words = 48 KB
#define GEMM_SMEM_BYTES (NST * STAGEW * 4)   // 147456

__global__ __launch_bounds__(256, 1) void gemm_tc(
    const float* __restrict__ A, const float* __restrict__ W,
    const float* __restrict__ bias0, const float* __restrict__ bias1,
    const float* __restrict__ bias2,
    float* __restrict__ C0, float* __restrict__ C1, float* __restrict__ C2,
    int round_out)
{
    extern __shared__ uint32_t smw[];
    const uint32_t sb = (uint32_t)__cvta_generic_to_shared(smw);

    const int t    = threadIdx.x;
    const int warp = t >> 5;
    const int lane = t & 31;
    const int wm   = warp >> 1;        // 0..3  (64-row m slice)
    const int wn   = warp & 1;         // 0..1  (64-col n slice)
    const int g    = lane >> 2;
    const int tt   = lane & 3;
    const int m0   = blockIdx.y * 256;
    const int n0   = blockIdx.x * 128;     // global row into packed W

    // staging coords: A has 2048 16B-chunks (8/thread), W has 1024 (4/thread)
    int arA[8], ajA[8], adwA[8];
#pragma unroll
    for (int e = 0; e < 8; e++) {
        int f   = e * 256 + t;
        arA[e]  = f >> 3;              // 0..255
        ajA[e]  = f & 7;
        adwA[e] = arA[e] * 32 + (ajA[e] ^ (arA[e] & 7)) * 4;
    }
    int arW[4], ajW[4], adwW[4];
#pragma unroll
    for (int e = 0; e < 4; e++) {
        int f   = e * 256 + t;
        arW[e]  = f >> 3;              // 0..127
        ajW[e]  = f & 7;
        adwW[e] = arW[e] * 32 + (ajW[e] ^ (arW[e] & 7)) * 4;
    }

    float acc[4][8][4];
#pragma unroll
    for (int mt = 0; mt < 4; mt++)
#pragma unroll
        for (int nt = 0; nt < 8; nt++)
#pragma unroll
            for (int r = 0; r < 4; r++) acc[mt][nt][r] = 0.f;

    // prologue: issue stages 0 and 1
#pragma unroll
    for (int s = 0; s < 2; s++) {
        uint32_t ba = sb + (s * STAGEW) * 4;
        uint32_t bw = ba + TILEWA * 4;
        const int ccol = s * KC;
#pragma unroll
        for (int e = 0; e < 8; e++)
            CP_ASYNC16(ba + adwA[e] * 4, A + (size_t)(m0 + arA[e]) * DM + ccol + ajA[e] * 4);
#pragma unroll
        for (int e = 0; e < 4; e++)
            CP_ASYNC16(bw + adwW[e] * 4, W + (size_t)(n0 + arW[e]) * DM + ccol + ajW[e] * 4);
        CP_COMMIT();
    }

    for (int ch = 0; ch < NCH; ch++) {
        CP_WAIT1();
        __syncthreads();

        if (ch + 2 < NCH) {
            const int s = (ch + 2) % NST;
            uint32_t ba = sb + (s * STAGEW) * 4;
            uint32_t bw = ba + TILEWA * 4;
            const int ccol = (ch + 2) * KC;
#pragma unroll
            for (int e = 0; e < 8; e++)
                CP_ASYNC16(ba + adwA[e] * 4, A + (size_t)(m0 + arA[e]) * DM + ccol + ajA[e] * 4);
#pragma unroll
            for (int e = 0; e < 4; e++)
                CP_ASYNC16(bw + adwW[e] * 4, W + (size_t)(n0 + arW[e]) * DM + ccol + ajW[e] * 4);
        }
        CP_COMMIT();

        const uint32_t* As = smw + (ch % NST) * STAGEW;
        const uint32_t* Ws = As + TILEWA;
#pragma unroll
        for (int ks = 0; ks < 4; ks++) {
            const int c0 = ((2 * ks) ^ g) * 4 + tt;
            const int c1 = ((2 * ks + 1) ^ g) * 4 + tt;
            uint32_t a[4][4], b[8][2];
#pragma unroll
            for (int mt = 0; mt < 4; mt++) {
                int R = (wm * 64 + mt * 16 + g) * 32;
                a[mt][0] = As[R + c0];
                a[mt][1] = As[R + 8 * 32 + c0];
                a[mt][2] = As[R + c1];
                a[mt][3] = As[R + 8 * 32 + c1];
            }
#pragma unroll
            for (int nt = 0; nt < 8; nt++) {
                int R = (wn * 64 + nt * 8 + g) * 32;
                b[nt][0] = Ws[R + c0];
                b[nt][1] = Ws[R + c1];
            }
#pragma unroll
            for (int mt = 0; mt < 4; mt++)
#pragma unroll
                for (int nt = 0; nt < 8; nt++)
                    mma8(acc[mt][nt], a[mt], b[nt]);
        }
    }

    // epilogue
    const int sel  = n0 >> 9;
    const int nloc = n0 & 511;
    const float* bias = (sel == 0) ? bias0 : (sel == 1) ? bias1 : bias2;
    float* C = (sel == 0) ? C0 : (sel == 1) ? C1 : C2;

#pragma unroll
    for (int mt = 0; mt < 4; mt++) {
        const int row0 = m0 + wm * 64 + mt * 16 + g;   // row0, row0+8 same window
#pragma unroll
        for (int nt = 0; nt < 8; nt++) {
            const int c = nloc + wn * 64 + nt * 8 + tt * 2;
            float b0 = bias[c], b1 = bias[c + 1];
            float v0 = acc[mt][nt][0] + b0, v1 = acc[mt][nt][1] + b1;
            float v2 = acc[mt][nt][2] + b0, v3 = acc[mt][nt][3] + b1;
            if (round_out) {
                // head-major: [win][head][wrow][c64]
                const int head = c >> 6, c64 = c & 63;
                const int win  = row0 >> 7, wrow = row0 & 127;
                float* base = C + (((size_t)(win * HEADS + head) * WSZ + wrow) * HD + c64);
                *(float2*)base            = make_float2(f2tf32f(v0), f2tf32f(v1));
                *(float2*)(base + 8 * HD) = make_float2(f2tf32f(v2), f2tf32f(v3));
            } else {
                float* p0 = C + (size_t)row0 * DM + c;
                float* p1 = C + (size_t)(row0 + 8) * DM + c;
                *(float2*)p0 = make_float2(v0, v1);
                *(float2*)p1 = make_float2(v2, v3);
            }
        }
    }
}

// ---------------------------------------------------------------------------
// Windowed attention v4 (unchanged, validated 113us): head-major QKV,
// all-cp.async staging, group0 = Q+K, group1 = V.
// ---------------------------------------------------------------------------
#define QP 68
#define SP 132
#define ATTN_SMEM_BYTES ((2 * 128 * QP + 128 * QP) * 4)   // 104448

__global__ __launch_bounds__(256, 2) void attn_kernel()
{
    extern __shared__ float smf[];
    float*    Qsf = smf;
    float*    Ksf = smf + 128 * QP;
    uint32_t* Qs  = (uint32_t*)Qsf;
    uint32_t* Ks  = (uint32_t*)Ksf;
    float*    Ss  = smf;                       // aliases Qs+Ks
    uint32_t* Ssu = (uint32_t*)Ss;
    float*    Vsf = smf + 2 * 128 * QP;
    uint32_t* Vs  = (uint32_t*)Vsf;
    const uint32_t sbQ = (uint32_t)__cvta_generic_to_shared(Qsf);
    const uint32_t sbK = (uint32_t)__cvta_generic_to_shared(Ksf);
    const uint32_t sbV = (uint32_t)__cvta_generic_to_shared(Vsf);

    const int h    = blockIdx.x;
    const int wdw  = blockIdx.y;
    const int t    = threadIdx.x;
    const int warp = t >> 5;
    const int lane = t & 31;
    const int wm   = warp >> 2;
    const int wn   = warp & 3;
    const int g    = lane >> 2;
    const int tt   = lane & 3;

    const size_t hbase = ((size_t)(wdw * HEADS + h)) * WSZ * HD;
    const size_t obase = (size_t)wdw * WSZ * DM + (size_t)h * HD;

#pragma unroll
    for (int it = 0; it < 8; it++) {
        int f   = it * 256 + t;
        int row = f >> 4;
        int c4  = (f & 15) << 2;
        CP_ASYNC16(sbQ + (row * QP + c4) * 4, g_q + hbase + row * HD + c4);
        CP_ASYNC16(sbK + (row * QP + c4) * 4, g_k + hbase + row * HD + c4);
    }
    CP_COMMIT();
#pragma unroll
    for (int it = 0; it < 8; it++) {
        int f   = it * 256 + t;
        int row = f >> 4;
        int c4  = (f & 15) << 2;
        CP_ASYNC16(sbV + (row * QP + c4) * 4, g_v + hbase + row * HD + c4);
    }
    CP_COMMIT();

    CP_WAIT1();
    __syncthreads();

    float sacc[4][4][4];
#pragma unroll
    for (int mt = 0; mt < 4; mt++)
#pragma unroll
        for (int nt = 0; nt < 4; nt++)
#pragma unroll
            for (int r = 0; r < 4; r++) sacc[mt][nt][r] = 0.f;

#pragma unroll
    for (int ks = 0; ks < 8; ks++) {
        uint32_t a[4][4], b[4][2];
#pragma unroll
        for (int mt = 0; mt < 4; mt++) {
            int ar = (wm * 64 + mt * 16 + g) * QP + ks * 8 + tt;
            a[mt][0] = Qs[ar];
            a[mt][1] = Qs[ar + 8 * QP];
            a[mt][2] = Qs[ar + 4];
            a[mt][3] = Qs[ar + 8 * QP + 4];
        }
#pragma unroll
        for (int nt = 0; nt < 4; nt++) {
            int br = (wn * 32 + nt * 8 + g) * QP + ks * 8 + tt;
            b[nt][0] = Ks[br];
            b[nt][1] = Ks[br + 4];
        }
#pragma unroll
        for (int mt = 0; mt < 4; mt++)
#pragma unroll
            for (int nt = 0; nt < 4; nt++)
                mma8(sacc[mt][nt], a[mt], b[nt]);
    }
    __syncthreads();

    const float scale = 0.125f;
#pragma unroll
    for (int mt = 0; mt < 4; mt++) {
        int r0 = (wm * 64 + mt * 16 + g) * SP;
        int r1 = r0 + 8 * SP;
#pragma unroll
        for (int nt = 0; nt < 4; nt++) {
            int c = wn * 32 + nt * 8 + tt * 2;
            Ss[r0 + c]     = sacc[mt][nt][0] * scale;
            Ss[r0 + c + 1] = sacc[mt][nt][1] * scale;
            Ss[r1 + c]     = sacc[mt][nt][2] * scale;
            Ss[r1 + c + 1] = sacc[mt][nt][3] * scale;
        }
    }
    __syncthreads();

    for (int r = warp * 16; r < warp * 16 + 16; r++) {
        float* srow = Ss + r * SP;
        float v0 = srow[lane];
        float v1 = srow[lane + 32];
        float v2 = srow[lane + 64];
        float v3 = srow[lane + 96];
        float mx = fmaxf(fmaxf(v0, v1), fmaxf(v2, v3));
#pragma unroll
        for (int o = 16; o > 0; o >>= 1)
            mx = fmaxf(mx, __shfl_xor_sync(0xffffffffu, mx, o));
        float e0 = fexp(v0 - mx);
        float e1 = fexp(v1 - mx);
        float e2 = fexp(v2 - mx);
        float e3 = fexp(v3 - mx);
        float s = e0 + e1 + e2 + e3;
#pragma unroll
        for (int o = 16; o > 0; o >>= 1)
            s += __shfl_xor_sync(0xffffffffu, s, o);
        float inv = 1.f / s;
        uint32_t* urow = (uint32_t*)srow;
        urow[lane]      = f2tf32(e0 * inv);
        urow[lane + 32] = f2tf32(e1 * inv);
        urow[lane + 64] = f2tf32(e2 * inv);
        urow[lane + 96] = f2tf32(e3 * inv);
    }
    CP_WAIT0();
    __syncthreads();

    float oacc[4][2][4];
#pragma unroll
    for (int mt = 0; mt < 4; mt++)
#pragma unroll
        for (int nt = 0; nt < 2; nt++)
#pragma unroll
            for (int r = 0; r < 4; r++) oacc[mt][nt][r] = 0.f;

#pragma unroll
    for (int ks = 0; ks < 16; ks++) {
        uint32_t a[4][4], b[2][2];
#pragma unroll
        for (int mt = 0; mt < 4; mt++) {
            int ar = (wm * 64 + mt * 16 + g) * SP + ks * 8 + tt;
            a[mt][0] = Ssu[ar];
            a[mt][1] = Ssu[ar + 8 * SP];
            a[mt][2] = Ssu[ar + 4];
            a[mt][3] = Ssu[ar + 8 * SP + 4];
        }
#pragma unroll
        for (int nt = 0; nt < 2; nt++) {
            int br = (ks * 8 + tt) * QP + wn * 16 + nt * 8 + g;
            b[nt][0] = Vs[br];
            b[nt][1] = Vs[br + 4 * QP];
        }
#pragma unroll
        for (int mt = 0; mt < 4; mt++)
#pragma unroll
            for (int nt = 0; nt < 2; nt++)
                mma8(oacc[mt][nt], a[mt], b[nt]);
    }

#pragma unroll
    for (int mt = 0; mt < 4; mt++) {
        const int row0 = wm * 64 + mt * 16 + g;
#pragma unroll
        for (int nt = 0; nt < 2; nt++) {
            const int c = wn * 16 + nt * 8 + tt * 2;
            float* p0 = g_ao + obase + (size_t)row0 * DM + c;
            float* p1 = g_ao + obase + (size_t)(row0 + 8) * DM + c;
            *(float2*)p0 = make_float2(f2tf32f(oacc[mt][nt][0]), f2tf32f(oacc[mt][nt][1]));
            *(float2*)p1 = make_float2(f2tf32f(oacc[mt][nt][2]), f2tf32f(oacc[mt][nt][3]));
        }
    }
}

// ---------------------------------------------------------------------------
// kernel_launch
// ---------------------------------------------------------------------------
extern "C" void kernel_launch(void* const* d_in, const int* in_sizes, int n_in,
                              void* d_out, int out_size)
{
    const float* x  = (const float*)d_in[0];
    const float* Wq = (const float*)d_in[1];
    const float* bq = (const float*)d_in[2];
    const float* Wk = (const float*)d_in[3];
    const float* bk = (const float*)d_in[4];
    const float* Wv = (const float*)d_in[5];
    const float* bv = (const float*)d_in[6];
    const float* Wp = (const float*)d_in[7];
    const float* bp = (const float*)d_in[8];
    float* out = (float*)d_out;

    void *pq, *pk, *pv, *pao, *pxr, *pwr;
    cudaGetSymbolAddress(&pq,  g_q);
    cudaGetSymbolAddress(&pk,  g_k);
    cudaGetSymbolAddress(&pv,  g_v);
    cudaGetSymbolAddress(&pao, g_ao);
    cudaGetSymbolAddress(&pxr, g_xr);
    cudaGetSymbolAddress(&pwr, g_wr);
    float* gq  = (float*)pq;
    float* gk  = (float*)pk;
    float* gv  = (float*)pv;
    float* gao = (float*)pao;
    float* gxr = (float*)pxr;
    float* gwr = (float*)pwr;

    cudaFuncSetAttribute(gemm_tc,
                         cudaFuncAttributeMaxDynamicSharedMemorySize, GEMM_SMEM_BYTES);
    cudaFuncSetAttribute(attn_kernel,
                         cudaFuncAttributeMaxDynamicSharedMemorySize, ATTN_SMEM_BYTES);

    // pre-pass
    const int NX4 = MTOT * DM / 4;
    cvt_tf32<<<(NX4 + 255) / 256, 256>>>(x, gxr, NX4);
    dim3 wgrid((DM * DM / 4 + 255) / 256, 4);
    cvt_w4<<<wgrid, 256>>>(Wq, Wk, Wv, Wp, gwr);

    dim3 gblk(256);

    // fused QKV projection: head-major rounded outputs (M tile = 256)
    dim3 qkvgrid(3 * DM / 128, MTOT / 256);   // (12, 128)
    gemm_tc<<<qkvgrid, gblk, GEMM_SMEM_BYTES>>>(gxr, gwr, bq, bk, bv,
                                                gq, gk, gv, 1);

    dim3 agrid(HEADS, NWIN);                  // (8, 256)
    attn_kernel<<<agrid, gblk, ATTN_SMEM_BYTES>>>();

    // output projection: flat fp32 output, not rounded
    dim3 pgrid(DM / 128, MTOT / 256);         // (4, 128)
    gemm_tc<<<pgrid, gblk, GEMM_SMEM_BYTES>>>(gao, gwr + 3 * DM * DM, bp, bp, bp,
                                              out, out, out, 0);
}